// round 12
// baseline (speedup 1.0000x reference)
#include <cuda_runtime.h>
#include <cstdint>

#define BB    8
#define NTOK  2048
#define LOW   512
#define HIGH  4096

// ---------------- scratch (static device memory; no allocs allowed) -------
__device__ float g_XT[(size_t)BB * LOW * NTOK];   // x^T       [b][l][n]
__device__ float g_G [(size_t)BB * LOW * LOW];    // x^T x
__device__ float g_GP[(size_t)4 * BB * LOW * LOW]; // G split-K partials
__device__ float g_M1[(size_t)BB * LOW * LOW];    // wq G
__device__ float g_V [(size_t)BB * NTOK * LOW];   // V
__device__ float g_E [(size_t)BB * LOW * HIGH];   // e -> combined attn
__device__ float g_T [(size_t)BB * HIGH * LOW];   // T2 = o_w @ attn^T
__device__ float g_S [(size_t)BB * LOW];
__device__ float g_U [(size_t)BB * HIGH];
__device__ float g_Vv[(size_t)BB * LOW];
// tf32-rounded copies of external inputs
__device__ float g_XR[(size_t)BB * NTOK * LOW];
__device__ float g_WQ[(size_t)LOW * LOW];
__device__ float g_WK[(size_t)HIGH * LOW];
__device__ float g_WV[(size_t)LOW * LOW];
__device__ float g_OW[(size_t)HIGH * HIGH];

// ---------------- helpers ---------------------------------------------------
__device__ __forceinline__ uint32_t smem_u32(const void* p) {
    return (uint32_t)__cvta_generic_to_shared(p);
}
__device__ __forceinline__ void cp16(uint32_t s, const void* g) {
    asm volatile("cp.async.cg.shared.global [%0], [%1], 16;" :: "r"(s), "l"(g));
}
__device__ __forceinline__ void cp_commit() {
    asm volatile("cp.async.commit_group;" ::: "memory");
}
template <int N>
__device__ __forceinline__ void cp_wait() {
    asm volatile("cp.async.wait_group %0;" :: "n"(N) : "memory");
}
__device__ __forceinline__ float tf32r(float f) {
    uint32_t r;
    asm("cvt.rna.tf32.f32 %0, %1;" : "=r"(r) : "f"(f));
    return __uint_as_float(r);
}
__device__ __forceinline__ void ldsm4(uint32_t& d0, uint32_t& d1,
                                      uint32_t& d2, uint32_t& d3, uint32_t a) {
    asm volatile("ldmatrix.sync.aligned.m8n8.x4.shared.b16 {%0,%1,%2,%3}, [%4];"
                 : "=r"(d0), "=r"(d1), "=r"(d2), "=r"(d3) : "r"(a));
}
__device__ __forceinline__ float warpSum(float v) {
#pragma unroll
    for (int o = 16; o > 0; o >>= 1) v += __shfl_xor_sync(0xffffffffu, v, o);
    return v;
}
__device__ __forceinline__ float warpMax(float v) {
#pragma unroll
    for (int o = 16; o > 0; o >>= 1) v = fmaxf(v, __shfl_xor_sync(0xffffffffu, v, o));
    return v;
}
__device__ __forceinline__ float warpMin(float v) {
#pragma unroll
    for (int o = 16; o > 0; o >>= 1) v = fminf(v, __shfl_xor_sync(0xffffffffu, v, o));
    return v;
}

// ---------------- tf32 rounding pass ----------------------------------------
__global__ __launch_bounds__(256) void round_tf32_kernel(
    float* __restrict__ d, const float* __restrict__ s, int n4)
{
    int i = blockIdx.x * 256 + threadIdx.x;
    if (i < n4) {
        float4 v = ((const float4*)s)[i];
        v.x = tf32r(v.x); v.y = tf32r(v.y); v.z = tf32r(v.z); v.w = tf32r(v.w);
        ((float4*)d)[i] = v;
    }
}

// ---------- fused round + transpose: XR = tf32(x); XT[b] = XR[b]^T ----------
__global__ __launch_bounds__(256) void round_transpose_kernel(
    float* __restrict__ xr, float* __restrict__ xt, const float* __restrict__ src)
{
    __shared__ float tile[32][33];
    const int b = blockIdx.z;
    const int n0 = blockIdx.x * 32, l0 = blockIdx.y * 32;
    const float* s = src + (size_t)b * NTOK * LOW;
    float* xrp = xr + (size_t)b * NTOK * LOW;
    float* d = xt + (size_t)b * LOW * NTOK;
    const int tx = threadIdx.x, ty = threadIdx.y;   // 32 x 8
#pragma unroll
    for (int r = 0; r < 32; r += 8) {
        size_t idx = (size_t)(n0 + ty + r) * LOW + l0 + tx;
        float v = tf32r(s[idx]);
        tile[ty + r][tx] = v;
        xrp[idx] = v;
    }
    __syncthreads();
#pragma unroll
    for (int r = 0; r < 32; r += 8)
        d[(size_t)(l0 + ty + r) * NTOK + n0 + tx] = tile[tx][ty + r];
}

// ---------------- split-K=4 reduce + tf32 round ------------------------------
__global__ __launch_bounds__(256) void reduce4_round_kernel(
    float* __restrict__ d, const float* __restrict__ p, int n4)
{
    int i = blockIdx.x * 256 + threadIdx.x;
    if (i < n4) {
        float4 a = ((const float4*)p)[i];
        float4 b = ((const float4*)p)[i + n4];
        float4 c = ((const float4*)p)[i + 2 * n4];
        float4 e = ((const float4*)p)[i + 3 * n4];
        a.x = tf32r(a.x + b.x + c.x + e.x);
        a.y = tf32r(a.y + b.y + c.y + e.y);
        a.z = tf32r(a.z + b.z + c.z + e.z);
        a.w = tf32r(a.w + b.w + c.w + e.w);
        ((float4*)d)[i] = a;
    }
}

// ---------------- column sums ------------------------------------------------
__global__ __launch_bounds__(256) void colsum_kernel(
    float* __restrict__ s, const float* __restrict__ x)
{
    const int b = blockIdx.y;
    const int l = blockIdx.x * 256 + threadIdx.x;
    const float* xp = x + (size_t)b * NTOK * LOW + l;
    float acc = 0.f;
    for (int n = 0; n < NTOK; n++) acc += xp[(size_t)n * LOW];
    s[b * LOW + l] = acc;
}

// ---------------- matvec -----------------------------------------------------
__global__ __launch_bounds__(256) void matvec_kernel(
    float* __restrict__ out, const float* __restrict__ W,
    const float* __restrict__ s, int rows)
{
    const int b = blockIdx.y;
    const int row = blockIdx.x * 8 + (threadIdx.x >> 5);
    const int lane = threadIdx.x & 31;
    if (row >= rows) return;
    const float* w = W + (size_t)row * LOW;
    const float* sv = s + b * LOW;
    float acc = 0.f;
    for (int i = lane; i < LOW; i += 32) acc += w[i] * sv[i];
    acc = warpSum(acc);
    if (lane == 0) out[(size_t)b * rows + row] = acc;
}

// ---------------- tf32 tensor-core GEMM --------------------------------------
// CTA tile 128x128x32; 4 warps, warp tile 64x64; 128 threads; 2 CTAs/SM.
// C[m,n] = alpha * sum_k A(m,k) * B(n,k) + bias
// blockIdx.z encodes (batch * nsplit + split); split offsets K by split*K.
#define Bb      128
#define BK      32
#define STAGES  3

template <int BIASROW>
__global__ __launch_bounds__(128, 2) void gemm_tc(
    int M, int N, int K,
    const float* __restrict__ A, int lda, long long strideA,
    const float* __restrict__ B, int ldb, long long strideB,
    float* __restrict__ C, int ldc, long long strideC,
    const float* __restrict__ bias, float alpha, int round_out,
    int nsplit, long long strideCsplit)
{
    constexpr int ATF = Bb * 36;

    extern __shared__ float sm[];
    float* sAst = sm;
    float* sBst = sm + STAGES * ATF;

    const int tid = threadIdx.x;
    const int wid = tid >> 5;
    const int lane = tid & 31;
    const int g = lane >> 2;
    const int t = lane & 3;
    const int warp_m = wid & 1;   // 2 warps over M (64 rows each)
    const int warp_n = wid >> 1;  // 2 warps over N (64 cols each)
    const int lmat = lane >> 3;
    const int lrow = lane & 7;

    const int bz = (int)blockIdx.z / nsplit;
    const int split = (int)blockIdx.z - bz * nsplit;
    A += (long long)bz * strideA + (long long)split * K;
    B += (long long)bz * strideB + (long long)split * K;
    C += (long long)bz * strideC + (long long)split * strideCsplit;
    const int m0 = blockIdx.y * Bb;
    const int n0 = blockIdx.x * Bb;

    auto loadA = [&](int st, int k0) {
        uint32_t s0 = smem_u32(sAst + st * ATF);
#pragma unroll
        for (int r = 0; r < 8; r++) {
            int i = tid + r * 128;
            int row = i >> 3, kq = i & 7;
            cp16(s0 + (uint32_t)(row * 144 + kq * 16),
                 &A[(long long)(m0 + row) * lda + k0 + kq * 4]);
        }
    };
    auto loadB = [&](int st, int k0) {
        uint32_t s0 = smem_u32(sBst + st * ATF);
#pragma unroll
        for (int r = 0; r < 8; r++) {
            int i = tid + r * 128;
            int row = i >> 3, kq = i & 7;
            cp16(s0 + (uint32_t)(row * 144 + kq * 16),
                 &B[(long long)(n0 + row) * ldb + k0 + kq * 4]);
        }
    };

    int a_off[4];
#pragma unroll
    for (int mf = 0; mf < 4; mf++)
        a_off[mf] = (warp_m * 64 + mf * 16 + ((lmat & 1) << 3) + lrow) * 36
                    + ((lmat >> 1) << 2);
    int b_off[4];
#pragma unroll
    for (int nf2 = 0; nf2 < 4; nf2++)
        b_off[nf2] = (warp_n * 64 + nf2 * 16 + ((lmat >> 1) << 3) + lrow) * 36
                     + ((lmat & 1) << 2);

    float acc[4][8][4];
#pragma unroll
    for (int i = 0; i < 4; i++)
#pragma unroll
        for (int j = 0; j < 8; j++)
#pragma unroll
            for (int r = 0; r < 4; r++) acc[i][j][r] = 0.f;

    const int niter = K >> 5;

#pragma unroll
    for (int s = 0; s < STAGES - 1; s++) {
        loadA(s, s * BK);
        loadB(s, s * BK);
        cp_commit();
    }

    for (int it = 0; it < niter; it++) {
        cp_wait<STAGES - 2>();
        __syncthreads();

        {
            int ns = it + STAGES - 1;
            if (ns < niter) {
                int st = ns % STAGES;
                loadA(st, ns * BK);
                loadB(st, ns * BK);
            }
            cp_commit();
        }

        const int stg = it % STAGES;
        const uint32_t sa = smem_u32(sAst + stg * ATF);
        const uint32_t sb = smem_u32(sBst + stg * ATF);

#pragma unroll
        for (int kk = 0; kk < BK; kk += 8) {
            uint32_t ua[4][4], ub[8][2];
#pragma unroll
            for (int mf = 0; mf < 4; mf++)
                ldsm4(ua[mf][0], ua[mf][1], ua[mf][2], ua[mf][3],
                      sa + (uint32_t)(a_off[mf] + kk) * 4u);
#pragma unroll
            for (int nf2 = 0; nf2 < 4; nf2++)
                ldsm4(ub[nf2 * 2][0], ub[nf2 * 2][1],
                      ub[nf2 * 2 + 1][0], ub[nf2 * 2 + 1][1],
                      sb + (uint32_t)(b_off[nf2] + kk) * 4u);
#pragma unroll
            for (int mf = 0; mf < 4; mf++)
#pragma unroll
                for (int nf = 0; nf < 8; nf++) {
                    asm volatile(
                        "mma.sync.aligned.m16n8k8.row.col.f32.tf32.tf32.f32 "
                        "{%0,%1,%2,%3}, {%4,%5,%6,%7}, {%8,%9}, {%0,%1,%2,%3};"
                        : "+f"(acc[mf][nf][0]), "+f"(acc[mf][nf][1]),
                          "+f"(acc[mf][nf][2]), "+f"(acc[mf][nf][3])
                        : "r"(ua[mf][0]), "r"(ua[mf][1]), "r"(ua[mf][2]), "r"(ua[mf][3]),
                          "r"(ub[nf][0]), "r"(ub[nf][1]));
                }
        }
    }

    // ---- epilogue ----
#pragma unroll
    for (int mf = 0; mf < 4; mf++) {
        const int row = m0 + warp_m * 64 + mf * 16 + g;
        float br0 = 0.f, br1 = 0.f;
        if (BIASROW) { br0 = bias[row]; br1 = bias[row + 8]; }
#pragma unroll
        for (int nf = 0; nf < 8; nf++) {
            const int col = n0 + warp_n * 64 + nf * 8 + t * 2;
            float b0 = br0, b1 = br0, c0 = br1, c1 = br1;
            if (!BIASROW && bias) {
                b0 = bias[col]; b1 = bias[col + 1]; c0 = b0; c1 = b1;
            } else if (!BIASROW) {
                b0 = b1 = c0 = c1 = 0.f;
            }
            float v00 = acc[mf][nf][0] * alpha + b0;
            float v01 = acc[mf][nf][1] * alpha + b1;
            float v10 = acc[mf][nf][2] * alpha + c0;
            float v11 = acc[mf][nf][3] * alpha + c1;
            if (round_out) {
                v00 = tf32r(v00); v01 = tf32r(v01);
                v10 = tf32r(v10); v11 = tf32r(v11);
            }
            *(float2*)&C[(long long)row * ldc + col] = make_float2(v00, v01);
            *(float2*)&C[(long long)(row + 8) * ldc + col] = make_float2(v10, v11);
        }
    }
}

// ---------------- combined softmax + bias rank-1 corrections ----------------
__global__ __launch_bounds__(256) void attn_combine_kernel(
    float* __restrict__ E, const int* __restrict__ linkage,
    const float* __restrict__ u, const float* __restrict__ vv,
    const float* __restrict__ bq, const float* __restrict__ bk)
{
    const int H = HIGH;
    const int l = blockIdx.x;
    const int b = blockIdx.y;
    float* row = E + ((long long)b * LOW + l) * H;
    const int* mrow = linkage + (long long)l * H;
    const float* urow = u + (long long)b * HIGH;

    __shared__ float se[HIGH];
    __shared__ unsigned char smk[HIGH];
    __shared__ float bufg[8], bufn[8], bufx[8], bufs1[8], bufs2[8];

    const int tid = threadIdx.x;
    const int lane = tid & 31, wid = tid >> 5;
    const float BIGV = 9.0e15f;
    const float ALPHA = 0.015625f;

    const float cq = bq[l];
    const float ck = vv[b * LOW + l] + (float)NTOK * cq;

    float gmax = -3.0e38f, mn = BIGV, mx = -BIGV;
    for (int h = tid; h < H; h += 256) {
        float v = row[h] + ALPHA * (cq * urow[h] + ck * bk[h]);
        int m = mrow[h];
        se[h] = v;
        smk[h] = (unsigned char)(m > 0);
        gmax = fmaxf(gmax, v);
        if (m > 0) { mn = fminf(mn, v); mx = fmaxf(mx, v); }
    }
    gmax = warpMax(gmax); mn = warpMin(mn); mx = warpMax(mx);
    if (lane == 0) { bufg[wid] = gmax; bufn[wid] = mn; bufx[wid] = mx; }
    __syncthreads();
    float GM = bufg[0], MN = bufn[0], MX = bufx[0];
#pragma unroll
    for (int i = 1; i < 8; i++) {
        GM = fmaxf(GM, bufg[i]); MN = fminf(MN, bufn[i]); MX = fmaxf(MX, bufx[i]);
    }

    float den = MX - MN;
    if (den == 0.f) den = 1e-6f;
    const float rden = 1.f / den;
    const float lmax = (MX - MN) * rden;

    float gsum = 0.f, lsum = 0.f;
    for (int h = tid; h < H; h += 256) {
        float v = se[h];
        gsum += __expf(v - GM);
        if (smk[h]) lsum += __expf((v - MN) * rden - lmax);
    }
    gsum = warpSum(gsum); lsum = warpSum(lsum);
    if (lane == 0) { bufs1[wid] = gsum; bufs2[wid] = lsum; }
    __syncthreads();
    float GS = 0.f, LS = 0.f;
#pragma unroll
    for (int i = 0; i < 8; i++) { GS += bufs1[i]; LS += bufs2[i]; }
    const float rg = 1.f / GS, rl = 1.f / LS;

    for (int h = tid; h < H; h += 256) {
        float v = se[h];
        float o = __expf(v - GM) * rg;
        if (smk[h]) o += __expf((v - MN) * rden - lmax) * rl;
        row[h] = tf32r(o);
    }
}

// ---------------- launch ----------------------------------------------------
extern "C" void kernel_launch(void* const* d_in, const int* in_sizes, int n_in,
                              void* d_out, int out_size)
{
    const float* x    = (const float*)d_in[0];
    const int*   link = (const int*)  d_in[1];
    const float* wq_w = (const float*)d_in[2];
    const float* wq_b = (const float*)d_in[3];
    const float* wk_w = (const float*)d_in[4];
    const float* wk_b = (const float*)d_in[5];
    const float* wv_w = (const float*)d_in[6];
    const float* wv_b = (const float*)d_in[7];
    const float* o_w  = (const float*)d_in[8];
    const float* o_b  = (const float*)d_in[9];
    float* out = (float*)d_out;

    float *XT, *G, *GP, *M1, *V, *E, *T2, *S, *U, *Vv;
    float *XR, *WQ, *WK, *WV, *OW;
    cudaGetSymbolAddress((void**)&XT, g_XT);
    cudaGetSymbolAddress((void**)&G,  g_G);
    cudaGetSymbolAddress((void**)&GP, g_GP);
    cudaGetSymbolAddress((void**)&M1, g_M1);
    cudaGetSymbolAddress((void**)&V,  g_V);
    cudaGetSymbolAddress((void**)&E,  g_E);
    cudaGetSymbolAddress((void**)&T2, g_T);
    cudaGetSymbolAddress((void**)&S,  g_S);
    cudaGetSymbolAddress((void**)&U,  g_U);
    cudaGetSymbolAddress((void**)&Vv, g_Vv);
    cudaGetSymbolAddress((void**)&XR, g_XR);
    cudaGetSymbolAddress((void**)&WQ, g_WQ);
    cudaGetSymbolAddress((void**)&WK, g_WK);
    cudaGetSymbolAddress((void**)&WV, g_WV);
    cudaGetSymbolAddress((void**)&OW, g_OW);

    constexpr int SMG = STAGES * 2 * (Bb * 36) * 4;    // 110592
    cudaFuncSetAttribute(gemm_tc<0>, cudaFuncAttributeMaxDynamicSharedMemorySize, SMG);
    cudaFuncSetAttribute(gemm_tc<1>, cudaFuncAttributeMaxDynamicSharedMemorySize, SMG);

    const int MT = BB * NTOK;
    dim3 blk(128);

    // --- pre-round weights to tf32 ---
    auto launch_round = [&](float* d, const float* s, long long n) {
        int n4 = (int)(n >> 2);
        round_tf32_kernel<<<(n4 + 255) / 256, 256>>>(d, s, n4);
    };
    launch_round(WQ, wq_w, (long long)LOW * LOW);
    launch_round(WK, wk_w, (long long)HIGH * LOW);
    launch_round(WV, wv_w, (long long)LOW * LOW);
    launch_round(OW, o_w,  (long long)HIGH * HIGH);

    // --- fused: XR = tf32(x), XT = XR^T ---
    round_transpose_kernel<<<dim3(NTOK / 32, LOW / 32, BB), dim3(32, 8)>>>(XR, XT, x);

    // V = x @ wv_w^T + wv_b (col bias)  [16384, 512]  (early: profiling slot)
    gemm_tc<0><<<dim3(LOW / 128, MT / 128, 1), blk, SMG>>>(
        MT, LOW, LOW, XR, LOW, 0, WV, LOW, 0, V, LOW, 0, wv_b, 1.f, 1, 1, 0);

    // --- bias-correction ingredients (exact, fp32) ---
    colsum_kernel<<<dim3(LOW / 256, BB), 256>>>(S, XR);
    matvec_kernel<<<dim3(HIGH / 8, BB), 256>>>(U, wk_w, S, HIGH);
    matvec_kernel<<<dim3(LOW / 8, BB), 256>>>(Vv, wq_w, S, LOW);

    // G partials: split-K=4 over n. z = batch*4 + split; K=512 each.
    gemm_tc<0><<<dim3(LOW / 128, LOW / 128, BB * 4), blk, SMG>>>(
        LOW, LOW, NTOK / 4,
        XT, NTOK, (long long)LOW * NTOK,
        XT, NTOK, (long long)LOW * NTOK,
        GP, LOW, (long long)LOW * LOW,
        nullptr, 1.f, 0, 4, (long long)BB * LOW * LOW);

    // G = tf32r(GP0 + GP1 + GP2 + GP3)
    {
        int n4 = (int)(((long long)BB * LOW * LOW) >> 2);
        reduce4_round_kernel<<<(n4 + 255) / 256, 256>>>(G, GP, n4);
    }

    // M1[b] = wq @ G[b]     [8][512][512]
    gemm_tc<0><<<dim3(LOW / 128, LOW / 128, BB), blk, SMG>>>(
        LOW, LOW, LOW,
        WQ, LOW, 0,
        G, LOW, (long long)LOW * LOW,
        M1, LOW, (long long)LOW * LOW,
        nullptr, 1.f, 1, 1, 0);

    // e[b] = M1[b] @ wk^T / sqrt(HIGH)     [8][512][4096]
    gemm_tc<0><<<dim3(HIGH / 128, LOW / 128, BB), blk, SMG>>>(
        LOW, HIGH, LOW,
        M1, LOW, (long long)LOW * LOW,
        WK, LOW, 0,
        E, HIGH, (long long)LOW * HIGH,
        nullptr, 0.015625f, 0, 1, 0);

    // E <- softmax_global + softmax_local (with rank-1 bias corrections)
    attn_combine_kernel<<<dim3(LOW, BB), 256>>>(E, link, U, Vv, wq_b, wk_b);

    // T2[b] = o_w @ attn[b]^T              [8][4096][512]
    gemm_tc<0><<<dim3(LOW / 128, HIGH / 128, BB), blk, SMG>>>(
        HIGH, LOW, HIGH,
        OW, HIGH, 0,
        E, HIGH, (long long)LOW * HIGH,
        T2, LOW, (long long)HIGH * LOW,
        nullptr, 1.f, 1, 1, 0);

    // out[b] = V[b] @ T2[b]^T + o_b (col bias)   [8][2048][4096]
    gemm_tc<0><<<dim3(HIGH / 128, NTOK / 128, BB), blk, SMG>>>(
        NTOK, HIGH, LOW,
        V, LOW, (long long)NTOK * LOW,
        T2, LOW, (long long)HIGH * LOW,
        out, HIGH, (long long)NTOK * HIGH,
        o_b, 1.f, 0, 1, 0);
}

// round 13
// speedup vs baseline: 1.6976x; 1.6976x over previous
#include <cuda_runtime.h>
#include <cuda_fp16.h>
#include <cstdint>

#define BB    8
#define NTOK  2048
#define LOW   512
#define HIGH  4096

// ---------------- scratch (static device memory; no allocs allowed) -------
__device__ float  g_XT[(size_t)BB * LOW * NTOK];   // tf32(x)^T  [b][l][n] (score path)
__device__ float  g_G [(size_t)BB * LOW * LOW];    // x^T x (tf32-rounded)
__device__ float  g_GP[(size_t)4 * BB * LOW * LOW];// G split-K partials
__device__ float  g_M1[(size_t)BB * LOW * LOW];    // wq G
__device__ float  g_E [(size_t)BB * LOW * HIGH];   // scores (fp32)
__device__ __half g_Eh[(size_t)BB * LOW * HIGH];   // combined attn probs (half)
__device__ __half g_Vh[(size_t)BB * NTOK * LOW];   // V (half)
__device__ __half g_Th[(size_t)BB * HIGH * LOW];   // T2 = o_w @ attn^T (half)
__device__ float  g_S [(size_t)BB * LOW];
__device__ float  g_U [(size_t)BB * HIGH];
__device__ float  g_Vv[(size_t)BB * LOW];
// rounded copies of external inputs
__device__ __half g_XRh[(size_t)BB * NTOK * LOW];  // half(x) (prob path)
__device__ float  g_WQ[(size_t)LOW * LOW];         // tf32
__device__ float  g_WK[(size_t)HIGH * LOW];        // tf32
__device__ __half g_WVh[(size_t)LOW * LOW];        // half
__device__ __half g_OWh[(size_t)HIGH * HIGH];      // half

// ---------------- helpers ---------------------------------------------------
__device__ __forceinline__ uint32_t smem_u32(const void* p) {
    return (uint32_t)__cvta_generic_to_shared(p);
}
__device__ __forceinline__ void cp16(uint32_t s, const void* g) {
    asm volatile("cp.async.cg.shared.global [%0], [%1], 16;" :: "r"(s), "l"(g));
}
__device__ __forceinline__ void cp_commit() {
    asm volatile("cp.async.commit_group;" ::: "memory");
}
template <int N>
__device__ __forceinline__ void cp_wait() {
    asm volatile("cp.async.wait_group %0;" :: "n"(N) : "memory");
}
__device__ __forceinline__ float tf32r(float f) {
    uint32_t r;
    asm("cvt.rna.tf32.f32 %0, %1;" : "=r"(r) : "f"(f));
    return __uint_as_float(r);
}
__device__ __forceinline__ void ldsm4(uint32_t& d0, uint32_t& d1,
                                      uint32_t& d2, uint32_t& d3, uint32_t a) {
    asm volatile("ldmatrix.sync.aligned.m8n8.x4.shared.b16 {%0,%1,%2,%3}, [%4];"
                 : "=r"(d0), "=r"(d1), "=r"(d2), "=r"(d3) : "r"(a));
}
__device__ __forceinline__ float warpSum(float v) {
#pragma unroll
    for (int o = 16; o > 0; o >>= 1) v += __shfl_xor_sync(0xffffffffu, v, o);
    return v;
}
__device__ __forceinline__ float warpMax(float v) {
#pragma unroll
    for (int o = 16; o > 0; o >>= 1) v = fmaxf(v, __shfl_xor_sync(0xffffffffu, v, o));
    return v;
}
__device__ __forceinline__ float warpMin(float v) {
#pragma unroll
    for (int o = 16; o > 0; o >>= 1) v = fminf(v, __shfl_xor_sync(0xffffffffu, v, o));
    return v;
}

// ---------------- rounding passes --------------------------------------------
__global__ __launch_bounds__(256) void round_tf32_kernel(
    float* __restrict__ d, const float* __restrict__ s, int n4)
{
    int i = blockIdx.x * 256 + threadIdx.x;
    if (i < n4) {
        float4 v = ((const float4*)s)[i];
        v.x = tf32r(v.x); v.y = tf32r(v.y); v.z = tf32r(v.z); v.w = tf32r(v.w);
        ((float4*)d)[i] = v;
    }
}
__global__ __launch_bounds__(256) void round_f16_kernel(
    __half* __restrict__ d, const float* __restrict__ s, int n4)
{
    int i = blockIdx.x * 256 + threadIdx.x;
    if (i < n4) {
        float4 v = ((const float4*)s)[i];
        ((__half2*)d)[i * 2]     = __floats2half2_rn(v.x, v.y);
        ((__half2*)d)[i * 2 + 1] = __floats2half2_rn(v.z, v.w);
    }
}

// ---- fused: XRh = half(x) (prob path); XT[b] = tf32(x)^T (score path) ------
__global__ __launch_bounds__(256) void round_transpose_kernel(
    __half* __restrict__ xrh, float* __restrict__ xt, const float* __restrict__ src)
{
    __shared__ float tile[32][33];
    const int b = blockIdx.z;
    const int n0 = blockIdx.x * 32, l0 = blockIdx.y * 32;
    const float* s = src + (size_t)b * NTOK * LOW;
    __half* xrp = xrh + (size_t)b * NTOK * LOW;
    float* d = xt + (size_t)b * LOW * NTOK;
    const int tx = threadIdx.x, ty = threadIdx.y;   // 32 x 8
#pragma unroll
    for (int r = 0; r < 32; r += 8) {
        size_t idx = (size_t)(n0 + ty + r) * LOW + l0 + tx;
        float v = s[idx];
        tile[ty + r][tx] = tf32r(v);
        xrp[idx] = __float2half_rn(v);
    }
    __syncthreads();
#pragma unroll
    for (int r = 0; r < 32; r += 8)
        d[(size_t)(l0 + ty + r) * NTOK + n0 + tx] = tile[tx][ty + r];
}

// ---------------- split-K=4 reduce + tf32 round ------------------------------
__global__ __launch_bounds__(256) void reduce4_round_kernel(
    float* __restrict__ d, const float* __restrict__ p, int n4)
{
    int i = blockIdx.x * 256 + threadIdx.x;
    if (i < n4) {
        float4 a = ((const float4*)p)[i];
        float4 b = ((const float4*)p)[i + n4];
        float4 c = ((const float4*)p)[i + 2 * n4];
        float4 e = ((const float4*)p)[i + 3 * n4];
        a.x = tf32r(a.x + b.x + c.x + e.x);
        a.y = tf32r(a.y + b.y + c.y + e.y);
        a.z = tf32r(a.z + b.z + c.z + e.z);
        a.w = tf32r(a.w + b.w + c.w + e.w);
        ((float4*)d)[i] = a;
    }
}

// ---------------- column sums (half input) -----------------------------------
__global__ __launch_bounds__(256) void colsum_kernel(
    float* __restrict__ s, const __half* __restrict__ x)
{
    const int b = blockIdx.y;
    const int l = blockIdx.x * 256 + threadIdx.x;
    const __half* xp = x + (size_t)b * NTOK * LOW + l;
    float acc = 0.f;
    for (int n = 0; n < NTOK; n++) acc += __half2float(xp[(size_t)n * LOW]);
    s[b * LOW + l] = acc;
}

// ---------------- matvec -----------------------------------------------------
__global__ __launch_bounds__(256) void matvec_kernel(
    float* __restrict__ out, const float* __restrict__ W,
    const float* __restrict__ s, int rows)
{
    const int b = blockIdx.y;
    const int row = blockIdx.x * 8 + (threadIdx.x >> 5);
    const int lane = threadIdx.x & 31;
    if (row >= rows) return;
    const float* w = W + (size_t)row * LOW;
    const float* sv = s + b * LOW;
    float acc = 0.f;
    for (int i = lane; i < LOW; i += 32) acc += w[i] * sv[i];
    acc = warpSum(acc);
    if (lane == 0) out[(size_t)b * rows + row] = acc;
}

// ---------------- tf32 tensor-core GEMM (R11 config — score path) ------------
#define Bb      128
#define BK      32
#define STAGES  3

template <int BIASROW>
__global__ __launch_bounds__(256, 2) void gemm_tc(
    int M, int N, int K,
    const float* __restrict__ A, int lda, long long strideA,
    const float* __restrict__ B, int ldb, long long strideB,
    float* __restrict__ C, int ldc, long long strideC,
    const float* __restrict__ bias, float alpha, int round_out,
    int nsplit, long long strideCsplit)
{
    constexpr int ATF = Bb * 36;
    extern __shared__ float sm[];
    float* sAst = sm;
    float* sBst = sm + STAGES * ATF;

    const int tid = threadIdx.x;
    const int wid = tid >> 5;
    const int lane = tid & 31;
    const int g = lane >> 2;
    const int t = lane & 3;
    const int warp_m = wid & 1;
    const int warp_n = wid >> 1;
    const int lmat = lane >> 3;
    const int lrow = lane & 7;

    const int bz = (int)blockIdx.z / nsplit;
    const int split = (int)blockIdx.z - bz * nsplit;
    A += (long long)bz * strideA + (long long)split * K;
    B += (long long)bz * strideB + (long long)split * K;
    C += (long long)bz * strideC + (long long)split * strideCsplit;
    const int m0 = blockIdx.y * Bb;
    const int n0 = blockIdx.x * Bb;

    auto loadA = [&](int st, int k0) {
        uint32_t s0 = smem_u32(sAst + st * ATF);
#pragma unroll
        for (int r = 0; r < 4; r++) {
            int i = tid + r * 256;
            int row = i >> 3, kq = i & 7;
            cp16(s0 + (uint32_t)(row * 144 + kq * 16),
                 &A[(long long)(m0 + row) * lda + k0 + kq * 4]);
        }
    };
    auto loadB = [&](int st, int k0) {
        uint32_t s0 = smem_u32(sBst + st * ATF);
#pragma unroll
        for (int r = 0; r < 4; r++) {
            int i = tid + r * 256;
            int row = i >> 3, kq = i & 7;
            cp16(s0 + (uint32_t)(row * 144 + kq * 16),
                 &B[(long long)(n0 + row) * ldb + k0 + kq * 4]);
        }
    };

    int a_off[4];
#pragma unroll
    for (int mf = 0; mf < 4; mf++)
        a_off[mf] = (warp_m * 64 + mf * 16 + ((lmat & 1) << 3) + lrow) * 36
                    + ((lmat >> 1) << 2);
    int b_off[2];
#pragma unroll
    for (int nf2 = 0; nf2 < 2; nf2++)
        b_off[nf2] = (warp_n * 32 + nf2 * 16 + ((lmat >> 1) << 3) + lrow) * 36
                     + ((lmat & 1) << 2);

    float acc[4][4][4];
#pragma unroll
    for (int i = 0; i < 4; i++)
#pragma unroll
        for (int j = 0; j < 4; j++)
#pragma unroll
            for (int r = 0; r < 4; r++) acc[i][j][r] = 0.f;

    const int niter = K >> 5;

#pragma unroll
    for (int s = 0; s < STAGES - 1; s++) {
        loadA(s, s * BK);
        loadB(s, s * BK);
        cp_commit();
    }

    for (int it = 0; it < niter; it++) {
        cp_wait<STAGES - 2>();
        __syncthreads();
        {
            int ns = it + STAGES - 1;
            if (ns < niter) {
                int st = ns % STAGES;
                loadA(st, ns * BK);
                loadB(st, ns * BK);
            }
            cp_commit();
        }
        const int stg = it % STAGES;
        const uint32_t sa = smem_u32(sAst + stg * ATF);
        const uint32_t sb = smem_u32(sBst + stg * ATF);

#pragma unroll
        for (int kk = 0; kk < BK; kk += 8) {
            uint32_t ua[4][4], ub[4][2];
#pragma unroll
            for (int mf = 0; mf < 4; mf++)
                ldsm4(ua[mf][0], ua[mf][1], ua[mf][2], ua[mf][3],
                      sa + (uint32_t)(a_off[mf] + kk) * 4u);
#pragma unroll
            for (int nf2 = 0; nf2 < 2; nf2++)
                ldsm4(ub[nf2 * 2][0], ub[nf2 * 2][1],
                      ub[nf2 * 2 + 1][0], ub[nf2 * 2 + 1][1],
                      sb + (uint32_t)(b_off[nf2] + kk) * 4u);
#pragma unroll
            for (int mf = 0; mf < 4; mf++)
#pragma unroll
                for (int nf = 0; nf < 4; nf++) {
                    asm volatile(
                        "mma.sync.aligned.m16n8k8.row.col.f32.tf32.tf32.f32 "
                        "{%0,%1,%2,%3}, {%4,%5,%6,%7}, {%8,%9}, {%0,%1,%2,%3};"
                        : "+f"(acc[mf][nf][0]), "+f"(acc[mf][nf][1]),
                          "+f"(acc[mf][nf][2]), "+f"(acc[mf][nf][3])
                        : "r"(ua[mf][0]), "r"(ua[mf][1]), "r"(ua[mf][2]), "r"(ua[mf][3]),
                          "r"(ub[nf][0]), "r"(ub[nf][1]));
                }
        }
    }

#pragma unroll
    for (int mf = 0; mf < 4; mf++) {
        const int row = m0 + warp_m * 64 + mf * 16 + g;
        float br0 = 0.f, br1 = 0.f;
        if (BIASROW) { br0 = bias[row]; br1 = bias[row + 8]; }
#pragma unroll
        for (int nf = 0; nf < 4; nf++) {
            const int col = n0 + warp_n * 32 + nf * 8 + t * 2;
            float b0 = br0, b1 = br0, c0 = br1, c1 = br1;
            if (!BIASROW && bias) {
                b0 = bias[col]; b1 = bias[col + 1]; c0 = b0; c1 = b1;
            } else if (!BIASROW) {
                b0 = b1 = c0 = c1 = 0.f;
            }
            float v00 = acc[mf][nf][0] * alpha + b0;
            float v01 = acc[mf][nf][1] * alpha + b1;
            float v10 = acc[mf][nf][2] * alpha + c0;
            float v11 = acc[mf][nf][3] * alpha + c1;
            if (round_out) {
                v00 = tf32r(v00); v01 = tf32r(v01);
                v10 = tf32r(v10); v11 = tf32r(v11);
            }
            *(float2*)&C[(long long)row * ldc + col] = make_float2(v00, v01);
            *(float2*)&C[(long long)(row + 8) * ldc + col] = make_float2(v10, v11);
        }
    }
}

// ---------------- fp16 tensor-core GEMM (prob path) --------------------------
// C[m,n] = alpha*sum_k A(m,k)B(n,k) + bias[n] (col bias, may be null)
// A [M,K] half k-contig, B [N,K] half k-contig. CTA 128x128xHBK, 8 warps 64x32.
// OUTHALF: 1 -> write __half C; 0 -> write float C.
#define HBK 64

template <int OUTHALF>
__global__ __launch_bounds__(256, 2) void gemm_f16(
    int M, int N, int K,
    const __half* __restrict__ A, int lda, long long strideA,
    const __half* __restrict__ B, int ldb, long long strideB,
    void* __restrict__ Cv, int ldc, long long strideC,
    const float* __restrict__ bias, float alpha)
{
    constexpr int ATF = Bb * 72;   // halfs per operand per stage (stride 72)
    extern __shared__ __half smh[];
    __half* sAst = smh;
    __half* sBst = smh + STAGES * ATF;

    const int tid = threadIdx.x;
    const int wid = tid >> 5;
    const int lane = tid & 31;
    const int g = lane >> 2;
    const int t = lane & 3;
    const int warp_m = wid & 1;
    const int warp_n = wid >> 1;
    const int lmat = lane >> 3;
    const int lrow = lane & 7;

    A += (long long)blockIdx.z * strideA;
    B += (long long)blockIdx.z * strideB;
    const int m0 = blockIdx.y * Bb;
    const int n0 = blockIdx.x * Bb;

    auto loadA = [&](int st, int k0) {
        uint32_t s0 = smem_u32(sAst + st * ATF);
#pragma unroll
        for (int r = 0; r < 4; r++) {
            int i = tid + r * 256;
            int row = i >> 3, kq = i & 7;
            cp16(s0 + (uint32_t)(row * 144 + kq * 16),
                 &A[(long long)(m0 + row) * lda + k0 + kq * 8]);
        }
    };
    auto loadB = [&](int st, int k0) {
        uint32_t s0 = smem_u32(sBst + st * ATF);
#pragma unroll
        for (int r = 0; r < 4; r++) {
            int i = tid + r * 256;
            int row = i >> 3, kq = i & 7;
            cp16(s0 + (uint32_t)(row * 144 + kq * 16),
                 &B[(long long)(n0 + row) * ldb + k0 + kq * 8]);
        }
    };

    // ldmatrix offsets in HALF units, stride 72 halfs per row.
    int a_off[4];
#pragma unroll
    for (int mf = 0; mf < 4; mf++)
        a_off[mf] = (warp_m * 64 + mf * 16 + ((lmat & 1) << 3) + lrow) * 72
                    + ((lmat >> 1) << 3);
    int b_off[2];
#pragma unroll
    for (int nf2 = 0; nf2 < 2; nf2++)
        b_off[nf2] = (warp_n * 32 + nf2 * 16 + ((lmat >> 1) << 3) + lrow) * 72
                     + ((lmat & 1) << 3);

    float acc[4][4][4];
#pragma unroll
    for (int i = 0; i < 4; i++)
#pragma unroll
        for (int j = 0; j < 4; j++)
#pragma unroll
            for (int r = 0; r < 4; r++) acc[i][j][r] = 0.f;

    const int niter = K / HBK;

#pragma unroll
    for (int s = 0; s < STAGES - 1; s++) {
        loadA(s, s * HBK);
        loadB(s, s * HBK);
        cp_commit();
    }

    for (int it = 0; it < niter; it++) {
        cp_wait<STAGES - 2>();
        __syncthreads();
        {
            int ns = it + STAGES - 1;
            if (ns < niter) {
                int st = ns % STAGES;
                loadA(st, ns * HBK);
                loadB(st, ns * HBK);
            }
            cp_commit();
        }
        const int stg = it % STAGES;
        const uint32_t sa = smem_u32(sAst + stg * ATF);
        const uint32_t sb = smem_u32(sBst + stg * ATF);

#pragma unroll
        for (int kk = 0; kk < HBK; kk += 16) {
            uint32_t ua[4][4], ub[4][2];
#pragma unroll
            for (int mf = 0; mf < 4; mf++)
                ldsm4(ua[mf][0], ua[mf][1], ua[mf][2], ua[mf][3],
                      sa + (uint32_t)(a_off[mf] + kk) * 2u);
#pragma unroll
            for (int nf2 = 0; nf2 < 2; nf2++)
                ldsm4(ub[nf2 * 2][0], ub[nf2 * 2][1],
                      ub[nf2 * 2 + 1][0], ub[nf2 * 2 + 1][1],
                      sb + (uint32_t)(b_off[nf2] + kk) * 2u);
#pragma unroll
            for (int mf = 0; mf < 4; mf++)
#pragma unroll
                for (int nf = 0; nf < 4; nf++) {
                    asm volatile(
                        "mma.sync.aligned.m16n8k16.row.col.f32.f16.f16.f32 "
                        "{%0,%1,%2,%3}, {%4,%5,%6,%7}, {%8,%9}, {%0,%1,%2,%3};"
                        : "+f"(acc[mf][nf][0]), "+f"(acc[mf][nf][1]),
                          "+f"(acc[mf][nf][2]), "+f"(acc[mf][nf][3])
                        : "r"(ua[mf][0]), "r"(ua[mf][1]), "r"(ua[mf][2]), "r"(ua[mf][3]),
                          "r"(ub[nf][0]), "r"(ub[nf][1]));
                }
        }
    }

    // ---- epilogue (col bias) ----
#pragma unroll
    for (int mf = 0; mf < 4; mf++) {
        const int row = m0 + warp_m * 64 + mf * 16 + g;
#pragma unroll
        for (int nf = 0; nf < 4; nf++) {
            const int col = n0 + warp_n * 32 + nf * 8 + t * 2;
            float b0 = 0.f, b1 = 0.f;
            if (bias) { b0 = bias[col]; b1 = bias[col + 1]; }
            float v00 = acc[mf][nf][0] * alpha + b0;
            float v01 = acc[mf][nf][1] * alpha + b1;
            float v10 = acc[mf][nf][2] * alpha + b0;
            float v11 = acc[mf][nf][3] * alpha + b1;
            if (OUTHALF) {
                __half* C = (__half*)Cv + blockIdx.z * strideC;
                *(__half2*)&C[(long long)row * ldc + col] = __floats2half2_rn(v00, v01);
                *(__half2*)&C[(long long)(row + 8) * ldc + col] = __floats2half2_rn(v10, v11);
            } else {
                float* C = (float*)Cv + blockIdx.z * strideC;
                *(float2*)&C[(long long)row * ldc + col] = make_float2(v00, v01);
                *(float2*)&C[(long long)(row + 8) * ldc + col] = make_float2(v10, v11);
            }
        }
    }
}

// ---------------- combined softmax + bias rank-1 corrections -----------------
// reads fp32 scores E, writes half probs Eh
__global__ __launch_bounds__(256) void attn_combine_kernel(
    const float* __restrict__ E, __half* __restrict__ Eh,
    const int* __restrict__ linkage,
    const float* __restrict__ u, const float* __restrict__ vv,
    const float* __restrict__ bq, const float* __restrict__ bk)
{
    const int H = HIGH;
    const int l = blockIdx.x;
    const int b = blockIdx.y;
    const float* row = E + ((long long)b * LOW + l) * H;
    __half* rowo = Eh + ((long long)b * LOW + l) * H;
    const int* mrow = linkage + (long long)l * H;
    const float* urow = u + (long long)b * HIGH;

    __shared__ float se[HIGH];
    __shared__ unsigned char smk[HIGH];
    __shared__ float bufg[8], bufn[8], bufx[8], bufs1[8], bufs2[8];

    const int tid = threadIdx.x;
    const int lane = tid & 31, wid = tid >> 5;
    const float BIGV = 9.0e15f;
    const float ALPHA = 0.015625f;

    const float cq = bq[l];
    const float ck = vv[b * LOW + l] + (float)NTOK * cq;

    float gmax = -3.0e38f, mn = BIGV, mx = -BIGV;
    for (int h = tid; h < H; h += 256) {
        float v = row[h] + ALPHA * (cq * urow[h] + ck * bk[h]);
        int m = mrow[h];
        se[h] = v;
        smk[h] = (unsigned char)(m > 0);
        gmax = fmaxf(gmax, v);
        if (m > 0) { mn = fminf(mn, v); mx = fmaxf(mx, v); }
    }
    gmax = warpMax(gmax); mn = warpMin(mn); mx = warpMax(mx);
    if (lane == 0) { bufg[wid] = gmax; bufn[wid] = mn; bufx[wid] = mx; }
    __syncthreads();
    float GM = bufg[0], MN = bufn[0], MX = bufx[0];
#pragma unroll
    for (int i = 1; i < 8; i++) {
        GM = fmaxf(GM, bufg[i]); MN = fminf(MN, bufn[i]); MX = fmaxf(MX, bufx[i]);
    }

    float den = MX - MN;
    if (den == 0.f) den = 1e-6f;
    const float rden = 1.f / den;
    const float lmax = (MX - MN) * rden;

    float gsum = 0.f, lsum = 0.f;
    for (int h = tid; h < H; h += 256) {
        float v = se[h];
        gsum += __expf(v - GM);
        if (smk[h]) lsum += __expf((v - MN) * rden - lmax);
    }
    gsum = warpSum(gsum); lsum = warpSum(lsum);
    if (lane == 0) { bufs1[wid] = gsum; bufs2[wid] = lsum; }
    __syncthreads();
    float GS = 0.f, LS = 0.f;
#pragma unroll
    for (int i = 0; i < 8; i++) { GS += bufs1[i]; LS += bufs2[i]; }
    const float rg = 1.f / GS, rl = 1.f / LS;

    for (int h = tid; h < H; h += 256) {
        float v = se[h];
        float o = __expf(v - GM) * rg;
        if (smk[h]) o += __expf((v - MN) * rden - lmax) * rl;
        rowo[h] = __float2half_rn(o);
    }
}

// ---------------- launch ----------------------------------------------------
extern "C" void kernel_launch(void* const* d_in, const int* in_sizes, int n_in,
                              void* d_out, int out_size)
{
    const float* x    = (const float*)d_in[0];
    const int*   link = (const int*)  d_in[1];
    const float* wq_w = (const float*)d_in[2];
    const float* wq_b = (const float*)d_in[3];
    const float* wk_w = (const float*)d_in[4];
    const float* wk_b = (const float*)d_in[5];
    const float* wv_w = (const float*)d_in[6];
    const float* wv_b = (const float*)d_in[7];
    const float* o_w  = (const float*)d_in[8];
    const float* o_b  = (const float*)d_in[9];
    float* out = (float*)d_out;

    float *XT, *G, *GP, *M1, *E, *S, *U, *Vv, *WQ, *WK;
    __half *Eh, *Vh, *Th, *XRh, *WVh, *OWh;
    cudaGetSymbolAddress((void**)&XT,  g_XT);
    cudaGetSymbolAddress((void**)&G,   g_G);
    cudaGetSymbolAddress((void**)&GP,  g_GP);
    cudaGetSymbolAddress((void**)&M1,  g_M1);
    cudaGetSymbolAddress((void**)&E,   g_E);
    cudaGetSymbolAddress((void**)&Eh,  g_Eh);
    cudaGetSymbolAddress((void**)&Vh,  g_Vh);
    cudaGetSymbolAddress((void**)&Th,  g_Th);
    cudaGetSymbolAddress((void**)&S,   g_S);
    cudaGetSymbolAddress((void**)&U,   g_U);
    cudaGetSymbolAddress((void**)&Vv,  g_Vv);
    cudaGetSymbolAddress((void**)&XRh, g_XRh);
    cudaGetSymbolAddress((void**)&WQ,  g_WQ);
    cudaGetSymbolAddress((void**)&WK,  g_WK);
    cudaGetSymbolAddress((void**)&WVh, g_WVh);
    cudaGetSymbolAddress((void**)&OWh, g_OWh);

    constexpr int SMG = STAGES * 2 * (Bb * 36) * 4;    // 110592 (tf32)
    constexpr int SMH = STAGES * 2 * (Bb * 72) * 2;    // 110592 (fp16)
    cudaFuncSetAttribute(gemm_tc<0>,  cudaFuncAttributeMaxDynamicSharedMemorySize, SMG);
    cudaFuncSetAttribute(gemm_f16<0>, cudaFuncAttributeMaxDynamicSharedMemorySize, SMH);
    cudaFuncSetAttribute(gemm_f16<1>, cudaFuncAttributeMaxDynamicSharedMemorySize, SMH);

    const int MT = BB * NTOK;
    dim3 blk(256);

    // --- pre-round weights ---
    {
        int n4 = (int)(((long long)LOW * LOW) >> 2);
        round_tf32_kernel<<<(n4 + 255) / 256, 256>>>(WQ, wq_w, n4);
        n4 = (int)(((long long)HIGH * LOW) >> 2);
        round_tf32_kernel<<<(n4 + 255) / 256, 256>>>(WK, wk_w, n4);
        n4 = (int)(((long long)LOW * LOW) >> 2);
        round_f16_kernel<<<(n4 + 255) / 256, 256>>>(WVh, wv_w, n4);
        n4 = (int)(((long long)HIGH * HIGH) >> 2);
        round_f16_kernel<<<(n4 + 255) / 256, 256>>>(OWh, o_w, n4);
    }

    // --- fused: XRh = half(x), XT = tf32(x)^T ---
    round_transpose_kernel<<<dim3(NTOK / 32, LOW / 32, BB), dim3(32, 8)>>>(XRh, XT, x);

    // V = x @ wv_w^T + wv_b (col bias) -> half   [16384, 512]
    gemm_f16<1><<<dim3(LOW / 128, MT / 128, 1), blk, SMH>>>(
        MT, LOW, LOW, XRh, LOW, 0, WVh, LOW, 0,
        (void*)Vh, LOW, 0, wv_b, 1.f);

    // --- bias-correction ingredients (exact, fp32; zero biases in practice) ---
    colsum_kernel<<<dim3(LOW / 256, BB), 256>>>(S, XRh);
    matvec_kernel<<<dim3(HIGH / 8, BB), 256>>>(U, wk_w, S, HIGH);
    matvec_kernel<<<dim3(LOW / 8, BB), 256>>>(Vv, wq_w, S, LOW);

    // G partials: split-K=4. z = batch*4 + split; K=512 each.
    gemm_tc<0><<<dim3(LOW / 128, LOW / 128, BB * 4), blk, SMG>>>(
        LOW, LOW, NTOK / 4,
        XT, NTOK, (long long)LOW * NTOK,
        XT, NTOK, (long long)LOW * NTOK,
        GP, LOW, (long long)LOW * LOW,
        nullptr, 1.f, 0, 4, (long long)BB * LOW * LOW);
    {
        int n4 = (int)(((long long)BB * LOW * LOW) >> 2);
        reduce4_round_kernel<<<(n4 + 255) / 256, 256>>>(G, GP, n4);
    }

    // M1[b] = wq @ G[b]   (tf32)
    gemm_tc<0><<<dim3(LOW / 128, LOW / 128, BB), blk, SMG>>>(
        LOW, LOW, LOW,
        WQ, LOW, 0,
        G, LOW, (long long)LOW * LOW,
        M1, LOW, (long long)LOW * LOW,
        nullptr, 1.f, 1, 1, 0);

    // e[b] = M1[b] @ wk^T / sqrt(HIGH)  (tf32, fp32 scores)
    gemm_tc<0><<<dim3(HIGH / 128, LOW / 128, BB), blk, SMG>>>(
        LOW, HIGH, LOW,
        M1, LOW, (long long)LOW * LOW,
        WK, LOW, 0,
        E, HIGH, (long long)LOW * HIGH,
        nullptr, 0.015625f, 0, 1, 0);

    // Eh <- half( softmax_global + softmax_local ) with rank-1 bias corrections
    attn_combine_kernel<<<dim3(LOW, BB), 256>>>(E, Eh, link, U, Vv, wq_b, wk_b);

    // T2[b] = o_w @ attn[b]^T -> half   [8][4096][512]
    gemm_f16<1><<<dim3(LOW / 128, HIGH / 128, BB), blk, SMH>>>(
        HIGH, LOW, HIGH,
        OWh, HIGH, 0,
        Eh, HIGH, (long long)LOW * HIGH,
        (void*)Th, LOW, (long long)HIGH * LOW,
        nullptr, 1.f);

    // out[b] = V[b] @ T2[b]^T + o_b -> fp32   [8][2048][4096]
    gemm_f16<0><<<dim3(HIGH / 128, NTOK / 128, BB), blk, SMH>>>(
        NTOK, HIGH, LOW,
        Vh, LOW, (long long)NTOK * LOW,
        Th, LOW, (long long)HIGH * LOW,
        (void*)out, HIGH, (long long)NTOK * HIGH,
        o_b, 1.f);
}

// round 14
// speedup vs baseline: 1.8729x; 1.1033x over previous
#include <cuda_runtime.h>
#include <cuda_fp16.h>
#include <cstdint>

#define BB    8
#define NTOK  2048
#define LOW   512
#define HIGH  4096

// ---------------- scratch (static device memory; no allocs allowed) -------
__device__ __half g_XTh[(size_t)BB * LOW * NTOK];  // half(x)^T [b][l][n]
__device__ float  g_GP[(size_t)4 * BB * LOW * LOW];// G split-K partials (fp32)
__device__ __half g_Gh[(size_t)BB * LOW * LOW];    // x^T x (half)
__device__ __half g_M1h[(size_t)BB * LOW * LOW];   // wq G (half)
__device__ float  g_E [(size_t)BB * LOW * HIGH];   // scores (fp32)
__device__ __half g_Eh[(size_t)BB * LOW * HIGH];   // combined attn probs (half)
__device__ __half g_Vh[(size_t)BB * NTOK * LOW];   // V (half)
__device__ __half g_Th[(size_t)BB * HIGH * LOW];   // T2 = o_w @ attn^T (half)
__device__ float  g_S [(size_t)BB * LOW];
__device__ float  g_U [(size_t)BB * HIGH];
__device__ float  g_Vv[(size_t)BB * LOW];
__device__ unsigned char g_MK[(size_t)LOW * HIGH]; // linkage > 0 mask
// half copies of external inputs
__device__ __half g_XRh[(size_t)BB * NTOK * LOW];
__device__ __half g_WQh[(size_t)LOW * LOW];
__device__ __half g_WKh[(size_t)HIGH * LOW];
__device__ __half g_WVh[(size_t)LOW * LOW];
__device__ __half g_OWh[(size_t)HIGH * HIGH];

// ---------------- helpers ---------------------------------------------------
__device__ __forceinline__ uint32_t smem_u32(const void* p) {
    return (uint32_t)__cvta_generic_to_shared(p);
}
__device__ __forceinline__ void cp16(uint32_t s, const void* g) {
    asm volatile("cp.async.cg.shared.global [%0], [%1], 16;" :: "r"(s), "l"(g));
}
__device__ __forceinline__ void cp_commit() {
    asm volatile("cp.async.commit_group;" ::: "memory");
}
template <int N>
__device__ __forceinline__ void cp_wait() {
    asm volatile("cp.async.wait_group %0;" :: "n"(N) : "memory");
}
__device__ __forceinline__ void ldsm4(uint32_t& d0, uint32_t& d1,
                                      uint32_t& d2, uint32_t& d3, uint32_t a) {
    asm volatile("ldmatrix.sync.aligned.m8n8.x4.shared.b16 {%0,%1,%2,%3}, [%4];"
                 : "=r"(d0), "=r"(d1), "=r"(d2), "=r"(d3) : "r"(a));
}
__device__ __forceinline__ float warpSum(float v) {
#pragma unroll
    for (int o = 16; o > 0; o >>= 1) v += __shfl_xor_sync(0xffffffffu, v, o);
    return v;
}
__device__ __forceinline__ float warpMax(float v) {
#pragma unroll
    for (int o = 16; o > 0; o >>= 1) v = fmaxf(v, __shfl_xor_sync(0xffffffffu, v, o));
    return v;
}
__device__ __forceinline__ float warpMin(float v) {
#pragma unroll
    for (int o = 16; o > 0; o >>= 1) v = fminf(v, __shfl_xor_sync(0xffffffffu, v, o));
    return v;
}

// ---------------- rounding / prep passes -------------------------------------
__global__ __launch_bounds__(256) void round_f16_kernel(
    __half* __restrict__ d, const float* __restrict__ s, int n4)
{
    int i = blockIdx.x * 256 + threadIdx.x;
    if (i < n4) {
        float4 v = ((const float4*)s)[i];
        ((__half2*)d)[i * 2]     = __floats2half2_rn(v.x, v.y);
        ((__half2*)d)[i * 2 + 1] = __floats2half2_rn(v.z, v.w);
    }
}

__global__ __launch_bounds__(256) void mask_kernel(
    unsigned char* __restrict__ mk, const int* __restrict__ link, int n)
{
    int i = blockIdx.x * 256 + threadIdx.x;
    if (i < n) {
        int4 v = ((const int4*)link)[i];
        uchar4 m = make_uchar4(v.x > 0, v.y > 0, v.z > 0, v.w > 0);
        ((uchar4*)mk)[i] = m;
    }
}

// ---- fused: XRh = half(x); XTh[b] = half(x)^T -------------------------------
__global__ __launch_bounds__(256) void round_transpose_kernel(
    __half* __restrict__ xrh, __half* __restrict__ xth, const float* __restrict__ src)
{
    __shared__ float tile[32][33];
    const int b = blockIdx.z;
    const int n0 = blockIdx.x * 32, l0 = blockIdx.y * 32;
    const float* s = src + (size_t)b * NTOK * LOW;
    __half* xrp = xrh + (size_t)b * NTOK * LOW;
    __half* d = xth + (size_t)b * LOW * NTOK;
    const int tx = threadIdx.x, ty = threadIdx.y;   // 32 x 8
#pragma unroll
    for (int r = 0; r < 32; r += 8) {
        size_t idx = (size_t)(n0 + ty + r) * LOW + l0 + tx;
        float v = s[idx];
        tile[ty + r][tx] = v;
        xrp[idx] = __float2half_rn(v);
    }
    __syncthreads();
#pragma unroll
    for (int r = 0; r < 32; r += 8)
        d[(size_t)(l0 + ty + r) * NTOK + n0 + tx] = __float2half_rn(tile[tx][ty + r]);
}

// ---------------- split-K=4 reduce -> half -----------------------------------
__global__ __launch_bounds__(256) void reduce4_half_kernel(
    __half* __restrict__ d, const float* __restrict__ p, int n4)
{
    int i = blockIdx.x * 256 + threadIdx.x;
    if (i < n4) {
        float4 a = ((const float4*)p)[i];
        float4 b = ((const float4*)p)[i + n4];
        float4 c = ((const float4*)p)[i + 2 * n4];
        float4 e = ((const float4*)p)[i + 3 * n4];
        ((__half2*)d)[i * 2]     = __floats2half2_rn(a.x + b.x + c.x + e.x,
                                                     a.y + b.y + c.y + e.y);
        ((__half2*)d)[i * 2 + 1] = __floats2half2_rn(a.z + b.z + c.z + e.z,
                                                     a.w + b.w + c.w + e.w);
    }
}

// ---------------- column sums (half input) -----------------------------------
__global__ __launch_bounds__(256) void colsum_kernel(
    float* __restrict__ s, const __half* __restrict__ x)
{
    const int b = blockIdx.y;
    const int l = blockIdx.x * 256 + threadIdx.x;
    const __half* xp = x + (size_t)b * NTOK * LOW + l;
    float acc = 0.f;
    for (int n = 0; n < NTOK; n++) acc += __half2float(xp[(size_t)n * LOW]);
    s[b * LOW + l] = acc;
}

// ---------------- matvec (exact fp32 weights) --------------------------------
__global__ __launch_bounds__(256) void matvec_kernel(
    float* __restrict__ out, const float* __restrict__ W,
    const float* __restrict__ s, int rows)
{
    const int b = blockIdx.y;
    const int row = blockIdx.x * 8 + (threadIdx.x >> 5);
    const int lane = threadIdx.x & 31;
    if (row >= rows) return;
    const float* w = W + (size_t)row * LOW;
    const float* sv = s + b * LOW;
    float acc = 0.f;
    for (int i = lane; i < LOW; i += 32) acc += w[i] * sv[i];
    acc = warpSum(acc);
    if (lane == 0) out[(size_t)b * rows + row] = acc;
}

// ---------------- fp16 tensor-core GEMM --------------------------------------
// C[m,n] = alpha*sum_k A(m,k)B(n,k) + bias[n] (col bias, may be null)
// A [M,K] half k-contig, B [N,K] half k-contig. CTA 128x128x64; 8 warps 64x32;
// 256 threads; 2 CTAs/SM. blockIdx.z = batch*nsplit + split (K offset split*K).
// OUTHALF: 1 -> __half C; 0 -> float C.
#define Bb      128
#define HBK     64
#define STAGES  3

template <int OUTHALF>
__global__ __launch_bounds__(256, 2) void gemm_f16(
    int M, int N, int K,
    const __half* __restrict__ A, int lda, long long strideA,
    const __half* __restrict__ B, int ldb, long long strideB,
    void* __restrict__ Cv, int ldc, long long strideC,
    const float* __restrict__ bias, float alpha,
    int nsplit, long long strideCsplit)
{
    constexpr int ATF = Bb * 72;
    extern __shared__ __half smh[];
    __half* sAst = smh;
    __half* sBst = smh + STAGES * ATF;

    const int tid = threadIdx.x;
    const int wid = tid >> 5;
    const int lane = tid & 31;
    const int g = lane >> 2;
    const int t = lane & 3;
    const int warp_m = wid & 1;
    const int warp_n = wid >> 1;
    const int lmat = lane >> 3;
    const int lrow = lane & 7;

    const int bz = (int)blockIdx.z / nsplit;
    const int split = (int)blockIdx.z - bz * nsplit;
    A += (long long)bz * strideA + (long long)split * K;
    B += (long long)bz * strideB + (long long)split * K;
    const long long coff = (long long)bz * strideC + (long long)split * strideCsplit;
    const int m0 = blockIdx.y * Bb;
    const int n0 = blockIdx.x * Bb;

    auto loadA = [&](int st, int k0) {
        uint32_t s0 = smem_u32(sAst + st * ATF);
#pragma unroll
        for (int r = 0; r < 4; r++) {
            int i = tid + r * 256;
            int row = i >> 3, kq = i & 7;
            cp16(s0 + (uint32_t)(row * 144 + kq * 16),
                 &A[(long long)(m0 + row) * lda + k0 + kq * 8]);
        }
    };
    auto loadB = [&](int st, int k0) {
        uint32_t s0 = smem_u32(sBst + st * ATF);
#pragma unroll
        for (int r = 0; r < 4; r++) {
            int i = tid + r * 256;
            int row = i >> 3, kq = i & 7;
            cp16(s0 + (uint32_t)(row * 144 + kq * 16),
                 &B[(long long)(n0 + row) * ldb + k0 + kq * 8]);
        }
    };

    int a_off[4];
#pragma unroll
    for (int mf = 0; mf < 4; mf++)
        a_off[mf] = (warp_m * 64 + mf * 16 + ((lmat & 1) << 3) + lrow) * 72
                    + ((lmat >> 1) << 3);
    int b_off[2];
#pragma unroll
    for (int nf2 = 0; nf2 < 2; nf2++)
        b_off[nf2] = (warp_n * 32 + nf2 * 16 + ((lmat >> 1) << 3) + lrow) * 72
                     + ((lmat & 1) << 3);

    float acc[4][4][4];
#pragma unroll
    for (int i = 0; i < 4; i++)
#pragma unroll
        for (int j = 0; j < 4; j++)
#pragma unroll
            for (int r = 0; r < 4; r++) acc[i][j][r] = 0.f;

    const int niter = K / HBK;

#pragma unroll
    for (int s = 0; s < STAGES - 1; s++) {
        loadA(s, s * HBK);
        loadB(s, s * HBK);
        cp_commit();
    }

    for (int it = 0; it < niter; it++) {
        cp_wait<STAGES - 2>();
        __syncthreads();
        {
            int ns = it + STAGES - 1;
            if (ns < niter) {
                int st = ns % STAGES;
                loadA(st, ns * HBK);
                loadB(st, ns * HBK);
            }
            cp_commit();
        }
        const int stg = it % STAGES;
        const uint32_t sa = smem_u32(sAst + stg * ATF);
        const uint32_t sb = smem_u32(sBst + stg * ATF);

#pragma unroll
        for (int kk = 0; kk < HBK; kk += 16) {
            uint32_t ua[4][4], ub[4][2];
#pragma unroll
            for (int mf = 0; mf < 4; mf++)
                ldsm4(ua[mf][0], ua[mf][1], ua[mf][2], ua[mf][3],
                      sa + (uint32_t)(a_off[mf] + kk) * 2u);
#pragma unroll
            for (int nf2 = 0; nf2 < 2; nf2++)
                ldsm4(ub[nf2 * 2][0], ub[nf2 * 2][1],
                      ub[nf2 * 2 + 1][0], ub[nf2 * 2 + 1][1],
                      sb + (uint32_t)(b_off[nf2] + kk) * 2u);
#pragma unroll
            for (int mf = 0; mf < 4; mf++)
#pragma unroll
                for (int nf = 0; nf < 4; nf++) {
                    asm volatile(
                        "mma.sync.aligned.m16n8k16.row.col.f32.f16.f16.f32 "
                        "{%0,%1,%2,%3}, {%4,%5,%6,%7}, {%8,%9}, {%0,%1,%2,%3};"
                        : "+f"(acc[mf][nf][0]), "+f"(acc[mf][nf][1]),
                          "+f"(acc[mf][nf][2]), "+f"(acc[mf][nf][3])
                        : "r"(ua[mf][0]), "r"(ua[mf][1]), "r"(ua[mf][2]), "r"(ua[mf][3]),
                          "r"(ub[nf][0]), "r"(ub[nf][1]));
                }
        }
    }

    // ---- epilogue (col bias) ----
#pragma unroll
    for (int mf = 0; mf < 4; mf++) {
        const int row = m0 + warp_m * 64 + mf * 16 + g;
#pragma unroll
        for (int nf = 0; nf < 4; nf++) {
            const int col = n0 + warp_n * 32 + nf * 8 + t * 2;
            float b0 = 0.f, b1 = 0.f;
            if (bias) { b0 = bias[col]; b1 = bias[col + 1]; }
            float v00 = acc[mf][nf][0] * alpha + b0;
            float v01 = acc[mf][nf][1] * alpha + b1;
            float v10 = acc[mf][nf][2] * alpha + b0;
            float v11 = acc[mf][nf][3] * alpha + b1;
            if (OUTHALF) {
                __half* C = (__half*)Cv + coff;
                *(__half2*)&C[(long long)row * ldc + col] = __floats2half2_rn(v00, v01);
                *(__half2*)&C[(long long)(row + 8) * ldc + col] = __floats2half2_rn(v10, v11);
            } else {
                float* C = (float*)Cv + coff;
                *(float2*)&C[(long long)row * ldc + col] = make_float2(v00, v01);
                *(float2*)&C[(long long)(row + 8) * ldc + col] = make_float2(v10, v11);
            }
        }
    }
}

// ---------------- combined softmax + bias rank-1 corrections -----------------
__global__ __launch_bounds__(256) void attn_combine_kernel(
    const float* __restrict__ E, __half* __restrict__ Eh,
    const unsigned char* __restrict__ mask,
    const float* __restrict__ u, const float* __restrict__ vv,
    const float* __restrict__ bq, const float* __restrict__ bk)
{
    const int H = HIGH;
    const int l = blockIdx.x;
    const int b = blockIdx.y;
    const float* row = E + ((long long)b * LOW + l) * H;
    __half* rowo = Eh + ((long long)b * LOW + l) * H;
    const unsigned char* mrow = mask + (long long)l * H;
    const float* urow = u + (long long)b * HIGH;

    __shared__ float se[HIGH];
    __shared__ unsigned char smk[HIGH];
    __shared__ float bufg[8], bufn[8], bufx[8], bufs1[8], bufs2[8];

    const int tid = threadIdx.x;
    const int lane = tid & 31, wid = tid >> 5;
    const float BIGV = 9.0e15f;
    const float ALPHA = 0.015625f;

    const float cq = bq[l];
    const float ck = vv[b * LOW + l] + (float)NTOK * cq;

    float gmax = -3.0e38f, mn = BIGV, mx = -BIGV;
    for (int h = tid; h < H; h += 256) {
        float v = row[h] + ALPHA * (cq * urow[h] + ck * bk[h]);
        unsigned char m = mrow[h];
        se[h] = v;
        smk[h] = m;
        gmax = fmaxf(gmax, v);
        if (m) { mn = fminf(mn, v); mx = fmaxf(mx, v); }
    }
    gmax = warpMax(gmax); mn = warpMin(mn); mx = warpMax(mx);
    if (lane == 0) { bufg[wid] = gmax; bufn[wid] = mn; bufx[wid] = mx; }
    __syncthreads();
    float GM = bufg[0], MN = bufn[0], MX = bufx[0];
#pragma unroll
    for (int i = 1; i < 8; i++) {
        GM = fmaxf(GM, bufg[i]); MN = fminf(MN, bufn[i]); MX = fmaxf(MX, bufx[i]);
    }

    float den = MX - MN;
    if (den == 0.f) den = 1e-6f;
    const float rden = 1.f / den;
    const float lmax = (MX - MN) * rden;

    float gsum = 0.f, lsum = 0.f;
    for (int h = tid; h < H; h += 256) {
        float v = se[h];
        gsum += __expf(v - GM);
        if (smk[h]) lsum += __expf((v - MN) * rden - lmax);
    }
    gsum = warpSum(gsum); lsum = warpSum(lsum);
    if (lane == 0) { bufs1[wid] = gsum; bufs2[wid] = lsum; }
    __syncthreads();
    float GS = 0.f, LS = 0.f;
#pragma unroll
    for (int i = 0; i < 8; i++) { GS += bufs1[i]; LS += bufs2[i]; }
    const float rg = 1.f / GS, rl = 1.f / LS;

    for (int h = tid; h < H; h += 256) {
        float v = se[h];
        float o = __expf(v - GM) * rg;
        if (smk[h]) o += __expf((v - MN) * rden - lmax) * rl;
        rowo[h] = __float2half_rn(o);
    }
}

// ---------------- launch ----------------------------------------------------
extern "C" void kernel_launch(void* const* d_in, const int* in_sizes, int n_in,
                              void* d_out, int out_size)
{
    const float* x    = (const float*)d_in[0];
    const int*   link = (const int*)  d_in[1];
    const float* wq_w = (const float*)d_in[2];
    const float* wq_b = (const float*)d_in[3];
    const float* wk_w = (const float*)d_in[4];
    const float* wk_b = (const float*)d_in[5];
    const float* wv_w = (const float*)d_in[6];
    const float* wv_b = (const float*)d_in[7];
    const float* o_w  = (const float*)d_in[8];
    const float* o_b  = (const float*)d_in[9];
    float* out = (float*)d_out;

    float *GP, *E, *S, *U, *Vv;
    __half *XTh, *Gh, *M1h, *Eh, *Vh, *Th, *XRh, *WQh, *WKh, *WVh, *OWh;
    unsigned char* MK;
    cudaGetSymbolAddress((void**)&XTh, g_XTh);
    cudaGetSymbolAddress((void**)&GP,  g_GP);
    cudaGetSymbolAddress((void**)&Gh,  g_Gh);
    cudaGetSymbolAddress((void**)&M1h, g_M1h);
    cudaGetSymbolAddress((void**)&E,   g_E);
    cudaGetSymbolAddress((void**)&Eh,  g_Eh);
    cudaGetSymbolAddress((void**)&Vh,  g_Vh);
    cudaGetSymbolAddress((void**)&Th,  g_Th);
    cudaGetSymbolAddress((void**)&S,   g_S);
    cudaGetSymbolAddress((void**)&U,   g_U);
    cudaGetSymbolAddress((void**)&Vv,  g_Vv);
    cudaGetSymbolAddress((void**)&MK,  g_MK);
    cudaGetSymbolAddress((void**)&XRh, g_XRh);
    cudaGetSymbolAddress((void**)&WQh, g_WQh);
    cudaGetSymbolAddress((void**)&WKh, g_WKh);
    cudaGetSymbolAddress((void**)&WVh, g_WVh);
    cudaGetSymbolAddress((void**)&OWh, g_OWh);

    constexpr int SMH = STAGES * 2 * (Bb * 72) * 2;    // 110592
    cudaFuncSetAttribute(gemm_f16<0>, cudaFuncAttributeMaxDynamicSharedMemorySize, SMH);
    cudaFuncSetAttribute(gemm_f16<1>, cudaFuncAttributeMaxDynamicSharedMemorySize, SMH);

    const int MT = BB * NTOK;
    dim3 blk(256);

    // --- pre-round weights to half; build linkage mask ---
    {
        int n4 = (int)(((long long)LOW * LOW) >> 2);
        round_f16_kernel<<<(n4 + 255) / 256, 256>>>(WQh, wq_w, n4);
        round_f16_kernel<<<(n4 + 255) / 256, 256>>>(WVh, wv_w, n4);
        n4 = (int)(((long long)HIGH * LOW) >> 2);
        round_f16_kernel<<<(n4 + 255) / 256, 256>>>(WKh, wk_w, n4);
        n4 = (int)(((long long)HIGH * HIGH) >> 2);
        round_f16_kernel<<<(n4 + 255) / 256, 256>>>(OWh, o_w, n4);
        int nm = (int)(((long long)LOW * HIGH) >> 2);
        mask_kernel<<<(nm + 255) / 256, 256>>>(MK, link, nm);
    }

    // --- fused: XRh = half(x), XTh = half(x)^T ---
    round_transpose_kernel<<<dim3(NTOK / 32, LOW / 32, BB), dim3(32, 8)>>>(XRh, XTh, x);

    // V = x @ wv_w^T + wv_b -> half   [16384, 512]
    gemm_f16<1><<<dim3(LOW / 128, MT / 128, 1), blk, SMH>>>(
        MT, LOW, LOW, XRh, LOW, 0, WVh, LOW, 0,
        (void*)Vh, LOW, 0, wv_b, 1.f, 1, 0);

    // --- bias-correction ingredients (exact fp32 weights) ---
    colsum_kernel<<<dim3(LOW / 256, BB), 256>>>(S, XRh);
    matvec_kernel<<<dim3(HIGH / 8, BB), 256>>>(U, wk_w, S, HIGH);
    matvec_kernel<<<dim3(LOW / 8, BB), 256>>>(Vv, wq_w, S, LOW);

    // G partials: split-K=4 (fp32 partials). z = batch*4 + split; K=512 each.
    gemm_f16<0><<<dim3(LOW / 128, LOW / 128, BB * 4), blk, SMH>>>(
        LOW, LOW, NTOK / 4,
        XTh, NTOK, (long long)LOW * NTOK,
        XTh, NTOK, (long long)LOW * NTOK,
        (void*)GP, LOW, (long long)LOW * LOW,
        nullptr, 1.f, 4, (long long)BB * LOW * LOW);
    {
        int n4 = (int)(((long long)BB * LOW * LOW) >> 2);
        reduce4_half_kernel<<<(n4 + 255) / 256, 256>>>(Gh, GP, n4);
    }

    // M1[b] = wq @ G[b] -> half  (G symmetric)  [8][512][512]
    gemm_f16<1><<<dim3(LOW / 128, LOW / 128, BB), blk, SMH>>>(
        LOW, LOW, LOW,
        WQh, LOW, 0,
        Gh, LOW, (long long)LOW * LOW,
        (void*)M1h, LOW, (long long)LOW * LOW,
        nullptr, 1.f, 1, 0);

    // e[b] = M1[b] @ wk^T / sqrt(HIGH) -> fp32 scores  [8][512][4096]
    gemm_f16<0><<<dim3(HIGH / 128, LOW / 128, BB), blk, SMH>>>(
        LOW, HIGH, LOW,
        M1h, LOW, (long long)LOW * LOW,
        WKh, LOW, 0,
        (void*)E, HIGH, (long long)LOW * HIGH,
        nullptr, 0.015625f, 1, 0);

    // Eh <- half( softmax_global + softmax_local ) with rank-1 bias corrections
    attn_combine_kernel<<<dim3(LOW, BB), 256>>>(E, Eh, MK, U, Vv, wq_b, wk_b);

    // T2[b] = o_w @ attn[b]^T -> half   [8][4096][512]
    gemm_f16<1><<<dim3(LOW / 128, HIGH / 128, BB), blk, SMH>>>(
        HIGH, LOW, HIGH,
        OWh, HIGH, 0,
        Eh, HIGH, (long long)LOW * HIGH,
        (void*)Th, LOW, (long long)HIGH * LOW,
        nullptr, 1.f, 1, 0);

    // out[b] = V[b] @ T2[b]^T + o_b -> fp32   [8][2048][4096]
    gemm_f16<0><<<dim3(HIGH / 128, NTOK / 128, BB), blk, SMH>>>(
        NTOK, HIGH, LOW,
        Vh, LOW, (long long)NTOK * LOW,
        Th, LOW, (long long)HIGH * LOW,
        (void*)out, HIGH, (long long)NTOK * HIGH,
        o_b, 1.f, 1, 0);
}